// round 3
// baseline (speedup 1.0000x reference)
#include <cuda_runtime.h>
#include <math.h>

#define NN   100000
#define EE   1600000
#define FIN  256
#define FOUT 128
#define SCAN_BLK 1024
#define NBLK ((NN + SCAN_BLK - 1) / SCAN_BLK)   // 98

// Scratch (static __device__)
__device__ float g_y[(size_t)NN * FOUT];   // y = (feature @ W) * dinv[row]
__device__ int   g_degi[NN];
__device__ float g_dinv[NN];
__device__ int   g_start[NN];
__device__ int   g_cursor[NN];
__device__ int   g_srow[EE];
__device__ int   g_bsum[NBLK];
__device__ float g_hsum[FOUT];

// ---------------------------------------------------------------------------
__global__ void k_zero(int n) {
    int i = blockIdx.x * blockDim.x + threadIdx.x;
    if (i < n) g_degi[i] = 0;
}

__global__ void k_deg(const int* __restrict__ col, int e) {
    int i = blockIdx.x * blockDim.x + threadIdx.x;
    if (i < e) atomicAdd(&g_degi[col[i]], 1);
}

__global__ void k_dinv(int n) {
    int i = blockIdx.x * blockDim.x + threadIdx.x;
    if (i < n) g_dinv[i] = rsqrtf((float)(g_degi[i] + 1));
}

__global__ void k_scan1() {
    __shared__ int sd[SCAN_BLK];
    int tx = threadIdx.x;
    int i = blockIdx.x * SCAN_BLK + tx;
    int v = (i < NN) ? g_degi[i] : 0;
    sd[tx] = v;
    __syncthreads();
#pragma unroll
    for (int off = 1; off < SCAN_BLK; off <<= 1) {
        int t = (tx >= off) ? sd[tx - off] : 0;
        __syncthreads();
        sd[tx] += t;
        __syncthreads();
    }
    if (i < NN) g_start[i] = sd[tx] - v;
    if (tx == SCAN_BLK - 1) g_bsum[blockIdx.x] = sd[tx];
}

__global__ void k_scan2() {
    int tx = threadIdx.x;
    if (tx < FOUT) g_hsum[tx] = 0.0f;
    if (tx == 0) {
        int acc = 0;
        for (int b = 0; b < NBLK; b++) {
            int t = g_bsum[b];
            g_bsum[b] = acc;
            acc += t;
        }
    }
}

__global__ void k_scan3() {
    int i = blockIdx.x * SCAN_BLK + threadIdx.x;
    if (i < NN) {
        int s = g_start[i] + g_bsum[blockIdx.x];
        g_start[i]  = s;
        g_cursor[i] = s;
    }
}

__global__ void k_sort(const int* __restrict__ row, const int* __restrict__ col, int e) {
    int i = blockIdx.x * blockDim.x + threadIdx.x;
    if (i < e) {
        int p = atomicAdd(&g_cursor[col[i]], 1);
        g_srow[p] = row[i];
    }
}

// ---------------------------------------------------------------------------
// SGEMM with packed f32x2 FMAs: y = (A @ W) * dinv[row].
// 128x128 tile, K-step 8, 8x8 micro-tile per thread (as 8x4 f32x2 pairs).
// A-tile stored DUPLICATED in smem so LDS.128 yields (a,a) packed pairs.
__global__ void __launch_bounds__(256, 2)
k_gemm(const float* __restrict__ A, const float* __restrict__ W, int N) {
    __shared__ float As2[8][264];   // [k][2*m duplicated], stride 264 (16B-aligned)
    __shared__ float Bs[8][132];    // [k][n]

    const int tx = threadIdx.x;
    const int block_row = blockIdx.x * 128;
    const int tid_r = tx >> 4;          // 0..15
    const int tid_c = tx & 15;          // 0..15

    unsigned long long acc[8][4];       // 8 rows x 4 f32x2 pairs (= 8 cols)
#pragma unroll
    for (int i = 0; i < 8; i++)
#pragma unroll
        for (int j = 0; j < 4; j++) acc[i][j] = 0ull;

    const int lrow = tx >> 1;           // 0..127
    const int half = tx & 1;
    const int gr_load = block_row + lrow;
    const int bk = tx >> 5;             // 0..7
    const int bc = tx & 31;             // 0..31

    for (int k0 = 0; k0 < FIN; k0 += 8) {
        float4 av = make_float4(0.f, 0.f, 0.f, 0.f);
        if (gr_load < N)
            av = *(const float4*)(A + (size_t)gr_load * FIN + k0 + half * 4);
        *(float2*)&As2[half * 4 + 0][2 * lrow] = make_float2(av.x, av.x);
        *(float2*)&As2[half * 4 + 1][2 * lrow] = make_float2(av.y, av.y);
        *(float2*)&As2[half * 4 + 2][2 * lrow] = make_float2(av.z, av.z);
        *(float2*)&As2[half * 4 + 3][2 * lrow] = make_float2(av.w, av.w);

        float4 bv = *(const float4*)(W + (size_t)(k0 + bk) * FOUT + bc * 4);
        *(float4*)&Bs[bk][bc * 4] = bv;

        __syncthreads();
#pragma unroll
        for (int kk = 0; kk < 8; kk++) {
            unsigned long long a2[8], b2[4];
            const ulonglong2* ap = (const ulonglong2*)&As2[kk][tid_r * 16];
#pragma unroll
            for (int i = 0; i < 4; i++) {
                ulonglong2 t = ap[i];
                a2[2 * i + 0] = t.x;
                a2[2 * i + 1] = t.y;
            }
            const ulonglong2* bp = (const ulonglong2*)&Bs[kk][tid_c * 8];
            {
                ulonglong2 t0 = bp[0];
                ulonglong2 t1 = bp[1];
                b2[0] = t0.x; b2[1] = t0.y; b2[2] = t1.x; b2[3] = t1.y;
            }
#pragma unroll
            for (int i = 0; i < 8; i++)
#pragma unroll
                for (int j = 0; j < 4; j++)
                    asm("fma.rn.f32x2 %0, %1, %2, %3;"
                        : "=l"(acc[i][j])
                        : "l"(a2[i]), "l"(b2[j]), "l"(acc[i][j]));
        }
        __syncthreads();
    }

#pragma unroll
    for (int i = 0; i < 8; i++) {
        int gr = block_row + tid_r * 8 + i;
        if (gr >= N) continue;
        float dv = g_dinv[gr];
#pragma unroll
        for (int j = 0; j < 4; j += 2) {
            float2 p0 = *(float2*)&acc[i][j + 0];
            float2 p1 = *(float2*)&acc[i][j + 1];
            float4 v;
            v.x = p0.x * dv;
            v.y = p0.y * dv;
            v.z = p1.x * dv;
            v.w = p1.y * dv;
            *(float4*)(g_y + (size_t)gr * FOUT + tid_c * 8 + 2 * j) = v;
        }
    }
}

// ---------------------------------------------------------------------------
// Gather-aggregate + fused epilogue. One warp per destination node.
__global__ void __launch_bounds__(256)
k_agg(const float* __restrict__ b, float* __restrict__ out, int N, int E) {
    __shared__ float hpart[FOUT];
    const int tx = threadIdx.x;
    if (tx < FOUT) hpart[tx] = 0.0f;
    __syncthreads();

    const int lane = tx & 31;
    const int warp = tx >> 5;
    const int node = blockIdx.x * 8 + warp;

    float4 v = make_float4(0.f, 0.f, 0.f, 0.f);
    if (node < N) {
        float4 acc = ((const float4*)(g_y + (size_t)node * FOUT))[lane];
        int s  = g_start[node];
        int e2 = (node + 1 < N) ? g_start[node + 1] : E;

        for (int base = s; base < e2; base += 32) {
            int cnt = min(32, e2 - base);
            int myidx = (lane < cnt) ? g_srow[base + lane] : 0;
            int j = 0;
            for (; j + 4 <= cnt; j += 4) {
                int r0 = __shfl_sync(0xffffffffu, myidx, j + 0);
                int r1 = __shfl_sync(0xffffffffu, myidx, j + 1);
                int r2 = __shfl_sync(0xffffffffu, myidx, j + 2);
                int r3 = __shfl_sync(0xffffffffu, myidx, j + 3);
                float4 v0 = ((const float4*)(g_y + (size_t)r0 * FOUT))[lane];
                float4 v1 = ((const float4*)(g_y + (size_t)r1 * FOUT))[lane];
                float4 v2 = ((const float4*)(g_y + (size_t)r2 * FOUT))[lane];
                float4 v3 = ((const float4*)(g_y + (size_t)r3 * FOUT))[lane];
                acc.x += v0.x + v1.x + v2.x + v3.x;
                acc.y += v0.y + v1.y + v2.y + v3.y;
                acc.z += v0.z + v1.z + v2.z + v3.z;
                acc.w += v0.w + v1.w + v2.w + v3.w;
            }
            for (; j < cnt; j++) {
                int r = __shfl_sync(0xffffffffu, myidx, j);
                float4 vv = ((const float4*)(g_y + (size_t)r * FOUT))[lane];
                acc.x += vv.x; acc.y += vv.y; acc.z += vv.z; acc.w += vv.w;
            }
        }

        float dv = g_dinv[node];
        float4 bv = ((const float4*)b)[lane];
        v.x = fmaxf(fmaf(acc.x, dv, bv.x), 0.0f);
        v.y = fmaxf(fmaf(acc.y, dv, bv.y), 0.0f);
        v.z = fmaxf(fmaf(acc.z, dv, bv.z), 0.0f);
        v.w = fmaxf(fmaf(acc.w, dv, bv.w), 0.0f);
        ((float4*)(out + (size_t)node * FOUT))[lane] = v;
    }

    atomicAdd(&hpart[lane * 4 + 0], v.x);
    atomicAdd(&hpart[lane * 4 + 1], v.y);
    atomicAdd(&hpart[lane * 4 + 2], v.z);
    atomicAdd(&hpart[lane * 4 + 3], v.w);
    __syncthreads();
    if (tx < FOUT) atomicAdd(&g_hsum[tx], hpart[tx]);
}

__global__ void k_h(float* __restrict__ hout, float ninv) {
    int j = threadIdx.x;
    float m = g_hsum[j] * ninv;
    hout[j] = 1.0f / (1.0f + expf(-m));
}

// ---------------------------------------------------------------------------
extern "C" void kernel_launch(void* const* d_in, const int* in_sizes, int n_in,
                              void* d_out, int out_size) {
    const float* feat = (const float*)d_in[0];
    const int*   ei   = (const int*)d_in[1];
    const float* W    = (const float*)d_in[2];
    const float* b    = (const float*)d_in[3];
    float* out = (float*)d_out;

    int N = in_sizes[0] / FIN;
    int E = in_sizes[1] / 2;
    const int* rowp = ei;
    const int* colp = ei + E;

    k_zero<<<(N + 255) / 256, 256>>>(N);
    k_deg<<<(E + 255) / 256, 256>>>(colp, E);
    k_dinv<<<(N + 255) / 256, 256>>>(N);
    k_scan1<<<NBLK, SCAN_BLK>>>();
    k_scan2<<<1, 128>>>();
    k_scan3<<<NBLK, SCAN_BLK>>>();
    k_sort<<<(E + 255) / 256, 256>>>(rowp, colp, E);
    k_gemm<<<(N + 127) / 128, 256>>>(feat, W, N);
    k_agg<<<(N + 7) / 8, 256>>>(b, out, N, E);
    k_h<<<1, FOUT>>>(out + (size_t)N * FOUT, 1.0f / (float)N);
}

// round 5
// speedup vs baseline: 1.5015x; 1.5015x over previous
#include <cuda_runtime.h>
#include <cuda_bf16.h>
#include <mma.h>
#include <math.h>
#include <cstdint>

using namespace nvcuda;

#define NN   100000
#define EE   1600000
#define FIN  256
#define FOUT 128
#define SCAN_BLK 1024
#define NBLK ((NN + SCAN_BLK - 1) / SCAN_BLK)   // 98

// Scratch (static __device__)
__device__ float g_y[(size_t)NN * FOUT];
__device__ int   g_degi[NN];
__device__ float g_dinv[NN];
__device__ int   g_start[NN];
__device__ int   g_cursor[NN];
__device__ int   g_srow[EE];
__device__ int   g_bsum[NBLK];
__device__ float g_hsum[FOUT];
__device__ __nv_bfloat16 g_Bhi[FIN * FOUT];   // W split: [k][n] bf16 hi
__device__ __nv_bfloat16 g_Blo[FIN * FOUT];   // [k][n] bf16 lo (residual)

// ---------------------------------------------------------------------------
__global__ void k_zero(int n) {
    int i = blockIdx.x * blockDim.x + threadIdx.x;
    if (i < n) g_degi[i] = 0;
}
__global__ void k_deg(const int* __restrict__ col, int e) {
    int i = blockIdx.x * blockDim.x + threadIdx.x;
    if (i < e) atomicAdd(&g_degi[col[i]], 1);
}
__global__ void k_dinv(int n) {
    int i = blockIdx.x * blockDim.x + threadIdx.x;
    if (i < n) g_dinv[i] = rsqrtf((float)(g_degi[i] + 1));
}
__global__ void k_scan1() {
    __shared__ int sd[SCAN_BLK];
    int tx = threadIdx.x;
    int i = blockIdx.x * SCAN_BLK + tx;
    int v = (i < NN) ? g_degi[i] : 0;
    sd[tx] = v;
    __syncthreads();
#pragma unroll
    for (int off = 1; off < SCAN_BLK; off <<= 1) {
        int t = (tx >= off) ? sd[tx - off] : 0;
        __syncthreads();
        sd[tx] += t;
        __syncthreads();
    }
    if (i < NN) g_start[i] = sd[tx] - v;
    if (tx == SCAN_BLK - 1) g_bsum[blockIdx.x] = sd[tx];
}
__global__ void k_scan2() {
    int tx = threadIdx.x;
    if (tx < FOUT) g_hsum[tx] = 0.0f;
    if (tx == 0) {
        int acc = 0;
        for (int b = 0; b < NBLK; b++) { int t = g_bsum[b]; g_bsum[b] = acc; acc += t; }
    }
}
__global__ void k_scan3() {
    int i = blockIdx.x * SCAN_BLK + threadIdx.x;
    if (i < NN) {
        int s = g_start[i] + g_bsum[blockIdx.x];
        g_start[i]  = s;
        g_cursor[i] = s;
    }
}
__global__ void k_sort(const int* __restrict__ row, const int* __restrict__ col, int e) {
    int i = blockIdx.x * blockDim.x + threadIdx.x;
    if (i < e) {
        int p = atomicAdd(&g_cursor[col[i]], 1);
        g_srow[p] = row[i];
    }
}

// W [k][n] fp32 -> bf16 hi/lo, same layout
__global__ void k_prep(const float* __restrict__ W) {
    int i = blockIdx.x * blockDim.x + threadIdx.x;
    if (i >= FIN * FOUT) return;
    float x = W[i];
    __nv_bfloat16 h = __float2bfloat16(x);
    __nv_bfloat16 l = __float2bfloat16(x - __bfloat162float(h));
    g_Bhi[i] = h;
    g_Blo[i] = l;
}

// ---------------------------------------------------------------------------
// bf16x3 GEMM via wmma (HMMA): y = (A @ W) * dinv[row].
// CTA tile 128x128, 8 warps (4x2), warp tile 32x64. K chunks of 64.
#define A_LD   80     // bf16 elems per A smem row (padded)
#define B_LD   136    // bf16 elems per B smem row (padded)
#define AH_OFF 0
#define AL_OFF 20480                  // 128*80*2
#define BH_OFF (AL_OFF + 20480)
#define BL_OFF (BH_OFF + 17408)      // 64*136*2
#define GEMM_SMEM (BL_OFF + 17408)   // 75776 B

__global__ void __launch_bounds__(256, 2)
k_gemm_mma(const float* __restrict__ A, int N) {
    extern __shared__ char sm[];
    __nv_bfloat16* As_h = (__nv_bfloat16*)(sm + AH_OFF);
    __nv_bfloat16* As_l = (__nv_bfloat16*)(sm + AL_OFF);
    __nv_bfloat16* Bs_h = (__nv_bfloat16*)(sm + BH_OFF);
    __nv_bfloat16* Bs_l = (__nv_bfloat16*)(sm + BL_OFF);

    const int tx = threadIdx.x;
    const int wid = tx >> 5;
    const int lane = tx & 31;
    const int wr = wid >> 1;          // 0..3  (32-row band)
    const int wc = wid & 1;           // 0..1  (64-col band)
    const int block_row = blockIdx.x * 128;

    wmma::fragment<wmma::accumulator, 16, 16, 16, float> acc[2][4];
#pragma unroll
    for (int i = 0; i < 2; i++)
#pragma unroll
        for (int j = 0; j < 4; j++) wmma::fill_fragment(acc[i][j], 0.0f);

    for (int kc = 0; kc < 4; kc++) {
        // --- A chunk: 128 rows x 64 k fp32 -> bf16 hi/lo ---
#pragma unroll
        for (int it = 0; it < 8; it++) {
            int t = tx + 256 * it;          // 0..2047
            int r = t >> 4, cq = t & 15;    // 16 float4 per row
            int gr = block_row + r;
            float4 f = make_float4(0.f, 0.f, 0.f, 0.f);
            if (gr < N) f = *(const float4*)(A + (size_t)gr * FIN + kc * 64 + cq * 4);
            __nv_bfloat162 h0 = __float22bfloat162_rn(make_float2(f.x, f.y));
            __nv_bfloat162 h1 = __float22bfloat162_rn(make_float2(f.z, f.w));
            float2 hf0 = __bfloat1622float2(h0);
            float2 hf1 = __bfloat1622float2(h1);
            __nv_bfloat162 l0 = __float22bfloat162_rn(make_float2(f.x - hf0.x, f.y - hf0.y));
            __nv_bfloat162 l1 = __float22bfloat162_rn(make_float2(f.z - hf1.x, f.w - hf1.y));
            uint2 hv = make_uint2(*(uint32_t*)&h0, *(uint32_t*)&h1);
            uint2 lv = make_uint2(*(uint32_t*)&l0, *(uint32_t*)&l1);
            *(uint2*)(As_h + r * A_LD + cq * 4) = hv;
            *(uint2*)(As_l + r * A_LD + cq * 4) = lv;
        }
        // --- B chunk: 64 k x 128 n bf16 hi/lo (copy) ---
#pragma unroll
        for (int it = 0; it < 4; it++) {
            int t = tx + 256 * it;          // 0..1023
            int k = t >> 4, ng = t & 15;    // 16 uint4 per row (128 bf16)
            uint4 vh = *(const uint4*)(g_Bhi + (size_t)(kc * 64 + k) * FOUT + ng * 8);
            uint4 vl = *(const uint4*)(g_Blo + (size_t)(kc * 64 + k) * FOUT + ng * 8);
            *(uint4*)(Bs_h + k * B_LD + ng * 8) = vh;
            *(uint4*)(Bs_l + k * B_LD + ng * 8) = vl;
        }
        __syncthreads();

#pragma unroll
        for (int kk = 0; kk < 4; kk++) {
            wmma::fragment<wmma::matrix_a, 16, 16, 16, __nv_bfloat16, wmma::row_major> ah[2], al[2];
#pragma unroll
            for (int i = 0; i < 2; i++) {
                const __nv_bfloat16* ap = As_h + (wr * 32 + i * 16) * A_LD + kk * 16;
                wmma::load_matrix_sync(ah[i], ap, A_LD);
                wmma::load_matrix_sync(al[i], ap + (AL_OFF - AH_OFF) / 2, A_LD);
            }
#pragma unroll
            for (int j = 0; j < 4; j++) {
                wmma::fragment<wmma::matrix_b, 16, 16, 16, __nv_bfloat16, wmma::row_major> bh, bl;
                const __nv_bfloat16* bp = Bs_h + (kk * 16) * B_LD + wc * 64 + j * 16;
                wmma::load_matrix_sync(bh, bp, B_LD);
                wmma::load_matrix_sync(bl, bp + (BL_OFF - BH_OFF) / 2, B_LD);
#pragma unroll
                for (int i = 0; i < 2; i++) {
                    wmma::mma_sync(acc[i][j], ah[i], bh, acc[i][j]);
                    wmma::mma_sync(acc[i][j], ah[i], bl, acc[i][j]);
                    wmma::mma_sync(acc[i][j], al[i], bh, acc[i][j]);
                }
            }
        }
        __syncthreads();
    }

    // Epilogue: per-warp staging (stride 68 floats -> conflict-free), scale by dinv
    float* stage = (float*)sm + wid * 2176;    // 32*68 floats per warp
#pragma unroll
    for (int i = 0; i < 2; i++)
#pragma unroll
        for (int j = 0; j < 4; j++)
            wmma::store_matrix_sync(stage + i * 16 * 68 + j * 16, acc[i][j], 68, wmma::mem_row_major);
    __syncwarp();

    int grow = block_row + wr * 32 + lane;
    if (grow < N) {
        float dv = g_dinv[grow];
        float* yp = g_y + (size_t)grow * FOUT + wc * 64;
        const float* sp = stage + lane * 68;
#pragma unroll
        for (int q = 0; q < 16; q++) {
            float4 v = *(const float4*)(sp + q * 4);
            v.x *= dv; v.y *= dv; v.z *= dv; v.w *= dv;
            *(float4*)(yp + q * 4) = v;
        }
    }
}

// ---------------------------------------------------------------------------
// Gather-aggregate + fused epilogue. One warp per destination node.
__global__ void __launch_bounds__(256)
k_agg(const float* __restrict__ b, float* __restrict__ out, int N, int E) {
    __shared__ float hpart[FOUT];
    const int tx = threadIdx.x;
    if (tx < FOUT) hpart[tx] = 0.0f;
    __syncthreads();

    const int lane = tx & 31;
    const int warp = tx >> 5;
    const int node = blockIdx.x * 8 + warp;

    float4 v = make_float4(0.f, 0.f, 0.f, 0.f);
    if (node < N) {
        float4 acc = ((const float4*)(g_y + (size_t)node * FOUT))[lane];
        int s  = g_start[node];
        int e2 = (node + 1 < N) ? g_start[node + 1] : E;

        for (int base = s; base < e2; base += 32) {
            int cnt = min(32, e2 - base);
            int myidx = (lane < cnt) ? g_srow[base + lane] : 0;
            int j = 0;
            for (; j + 4 <= cnt; j += 4) {
                int r0 = __shfl_sync(0xffffffffu, myidx, j + 0);
                int r1 = __shfl_sync(0xffffffffu, myidx, j + 1);
                int r2 = __shfl_sync(0xffffffffu, myidx, j + 2);
                int r3 = __shfl_sync(0xffffffffu, myidx, j + 3);
                float4 v0 = ((const float4*)(g_y + (size_t)r0 * FOUT))[lane];
                float4 v1 = ((const float4*)(g_y + (size_t)r1 * FOUT))[lane];
                float4 v2 = ((const float4*)(g_y + (size_t)r2 * FOUT))[lane];
                float4 v3 = ((const float4*)(g_y + (size_t)r3 * FOUT))[lane];
                acc.x += v0.x + v1.x + v2.x + v3.x;
                acc.y += v0.y + v1.y + v2.y + v3.y;
                acc.z += v0.z + v1.z + v2.z + v3.z;
                acc.w += v0.w + v1.w + v2.w + v3.w;
            }
            for (; j < cnt; j++) {
                int r = __shfl_sync(0xffffffffu, myidx, j);
                float4 vv = ((const float4*)(g_y + (size_t)r * FOUT))[lane];
                acc.x += vv.x; acc.y += vv.y; acc.z += vv.z; acc.w += vv.w;
            }
        }

        float dv = g_dinv[node];
        float4 bv = ((const float4*)b)[lane];
        v.x = fmaxf(fmaf(acc.x, dv, bv.x), 0.0f);
        v.y = fmaxf(fmaf(acc.y, dv, bv.y), 0.0f);
        v.z = fmaxf(fmaf(acc.z, dv, bv.z), 0.0f);
        v.w = fmaxf(fmaf(acc.w, dv, bv.w), 0.0f);
        ((float4*)(out + (size_t)node * FOUT))[lane] = v;
    }

    atomicAdd(&hpart[lane * 4 + 0], v.x);
    atomicAdd(&hpart[lane * 4 + 1], v.y);
    atomicAdd(&hpart[lane * 4 + 2], v.z);
    atomicAdd(&hpart[lane * 4 + 3], v.w);
    __syncthreads();
    if (tx < FOUT) atomicAdd(&g_hsum[tx], hpart[tx]);
}

__global__ void k_h(float* __restrict__ hout, float ninv) {
    int j = threadIdx.x;
    float m = g_hsum[j] * ninv;
    hout[j] = 1.0f / (1.0f + expf(-m));
}

// ---------------------------------------------------------------------------
extern "C" void kernel_launch(void* const* d_in, const int* in_sizes, int n_in,
                              void* d_out, int out_size) {
    const float* feat = (const float*)d_in[0];
    const int*   ei   = (const int*)d_in[1];
    const float* W    = (const float*)d_in[2];
    const float* b    = (const float*)d_in[3];
    float* out = (float*)d_out;

    int N = in_sizes[0] / FIN;
    int E = in_sizes[1] / 2;
    const int* rowp = ei;
    const int* colp = ei + E;

    cudaFuncSetAttribute(k_gemm_mma, cudaFuncAttributeMaxDynamicSharedMemorySize, GEMM_SMEM);

    k_zero<<<(N + 255) / 256, 256>>>(N);
    k_deg<<<(E + 255) / 256, 256>>>(colp, E);
    k_dinv<<<(N + 255) / 256, 256>>>(N);
    k_scan1<<<NBLK, SCAN_BLK>>>();
    k_scan2<<<1, 128>>>();
    k_scan3<<<NBLK, SCAN_BLK>>>();
    k_sort<<<(E + 255) / 256, 256>>>(rowp, colp, E);
    k_prep<<<(FIN * FOUT + 255) / 256, 256>>>(W);
    k_gemm_mma<<<(N + 127) / 128, 256, GEMM_SMEM>>>(feat, N);
    k_agg<<<(N + 7) / 8, 256>>>(b, out, N, E);
    k_h<<<1, FOUT>>>(out + (size_t)N * FOUT, 1.0f / (float)N);
}